// round 1
// baseline (speedup 1.0000x reference)
#include <cuda_runtime.h>

#define Bn 4
#define Pn 8
#define Vn 2048
#define En 2048
#define Fn 4096
#define TILES 16
#define TPB 128              // 128 verts per block
#define BIGF 3.402823466e38f

__device__ int   g_mask_is_int32;
__device__ float g_part_sum[Bn * Pn * TILES];
__device__ float g_part_cnt[Bn * Pn * TILES];

// ---------------------------------------------------------------------------
// Detect whether boundary_mask was shipped as int32 (widened bool) or as
// 1-byte bool. int32 little-endian 0/1 values have every byte at offset
// i%4 != 0 equal to zero; a random 0/1 byte mask cannot (P ~ 2^-3072).
// ---------------------------------------------------------------------------
__global__ void detect_mask_kernel(const unsigned char* __restrict__ bm) {
    __shared__ int any_nonzero;
    if (threadIdx.x == 0) any_nonzero = 0;
    __syncthreads();
    for (int i = threadIdx.x; i < 4096; i += blockDim.x) {
        if ((i & 3) != 0 && bm[i] != 0) atomicOr(&any_nonzero, 1);
    }
    __syncthreads();
    if (threadIdx.x == 0) g_mask_is_int32 = (any_nonzero == 0) ? 1 : 0;
}

// ---------------------------------------------------------------------------
// Chamfer main kernel: grid (TILES, P, B), TPB threads, one vertex per thread.
// Shared holds the full edgemap for (b,p) pre-transformed to (|e|^2, -2ex, -2ey).
// Inner loop: d2' = fma(px, -2ex, fma(py, -2ey, |e|^2)); min. |p|^2 added after.
// ---------------------------------------------------------------------------
__global__ void __launch_bounds__(TPB)
chamfer_kernel(const float* __restrict__ xs,
               const float* __restrict__ pm,
               const float* __restrict__ em,
               const int*   __restrict__ lens,
               const void*  __restrict__ bmask)
{
    __shared__ float4 s_edge[En];
    __shared__ float  s_rs[TPB / 32];
    __shared__ float  s_rc[TPB / 32];

    const int tile = blockIdx.x;
    const int p    = blockIdx.y;
    const int b    = blockIdx.z;
    const int tid  = threadIdx.x;

    // load + precompute edge table
    const float* embase = em + ((size_t)(b * Pn + p)) * En * 2;
    #pragma unroll
    for (int e = tid; e < En; e += TPB) {
        float ex = embase[2 * e + 0];
        float ey = embase[2 * e + 1];
        s_edge[e] = make_float4(fmaf(ex, ex, ey * ey), -2.0f * ex, -2.0f * ey, 0.0f);
    }
    const int L = lens[b * Pn + p];

    // per-thread vertex projection
    const int v = tile * TPB + tid;
    const float* xv = xs + ((size_t)b * Vn + v) * 3;
    const float x = xv[0], y = xv[1], z = xv[2];
    const float* M = pm + p * 12;
    const float q0 = M[0] * x + M[1] * y + M[2]  * z + M[3];
    const float q1 = M[4] * x + M[5] * y + M[6]  * z + M[7];
    const float q2 = M[8] * x + M[9] * y + M[10] * z + M[11];
    const float px = q0 / q2;
    const float py = q1 / q2;

    __syncthreads();

    // min over valid edges, 4 independent accumulators
    float m0 = BIGF, m1 = BIGF, m2 = BIGF, m3 = BIGF;
    const int L4 = L & ~3;
    #pragma unroll 2
    for (int e = 0; e < L4; e += 4) {
        float4 a = s_edge[e + 0];
        float4 c = s_edge[e + 1];
        float4 d = s_edge[e + 2];
        float4 f = s_edge[e + 3];
        m0 = fminf(m0, fmaf(px, a.y, fmaf(py, a.z, a.x)));
        m1 = fminf(m1, fmaf(px, c.y, fmaf(py, c.z, c.x)));
        m2 = fminf(m2, fmaf(px, d.y, fmaf(py, d.z, d.x)));
        m3 = fminf(m3, fmaf(px, f.y, fmaf(py, f.z, f.x)));
    }
    for (int e = L4; e < L; ++e) {
        float4 a = s_edge[e];
        m0 = fminf(m0, fmaf(px, a.y, fmaf(py, a.z, a.x)));
    }
    float dmin = fminf(fminf(m0, m1), fminf(m2, m3)) + fmaf(px, px, py * py);

    // boundary mask
    const int midx = (b * Pn + p) * Vn + v;
    float w;
    if (g_mask_is_int32) w = (((const int*)bmask)[midx] != 0) ? 1.0f : 0.0f;
    else                 w = (((const unsigned char*)bmask)[midx] != 0) ? 1.0f : 0.0f;

    float cs = w * dmin;   // contribution to sum
    float cc = w;          // contribution to count

    // block reduction (deterministic: fixed shuffle tree)
    #pragma unroll
    for (int off = 16; off >= 1; off >>= 1) {
        cs += __shfl_down_sync(0xffffffffu, cs, off);
        cc += __shfl_down_sync(0xffffffffu, cc, off);
    }
    const int wid = tid >> 5;
    if ((tid & 31) == 0) { s_rs[wid] = cs; s_rc[wid] = cc; }
    __syncthreads();
    if (tid == 0) {
        float ts = 0.0f, tc = 0.0f;
        #pragma unroll
        for (int i = 0; i < TPB / 32; ++i) { ts += s_rs[i]; tc += s_rc[i]; }
        const int slot = (b * Pn + p) * TILES + tile;
        g_part_sum[slot] = ts;
        g_part_cnt[slot] = tc;
    }
}

// ---------------------------------------------------------------------------
// Volume constraint: one block per batch, deterministic tree reduction in fp64.
// ---------------------------------------------------------------------------
__global__ void __launch_bounds__(256)
volume_kernel(const float* __restrict__ xs,
              const int*   __restrict__ faces,
              const float* __restrict__ tv,
              float* __restrict__ out)
{
    const int b   = blockIdx.x;
    const int tid = threadIdx.x;
    __shared__ double sred[256];

    const float* base = xs + (size_t)b * Vn * 3;
    double acc = 0.0;
    for (int f = tid; f < Fn; f += 256) {
        const int* fi = faces + ((size_t)b * Fn + f) * 3;
        const float* a0 = base + (size_t)fi[0] * 3;
        const float* a1 = base + (size_t)fi[1] * 3;
        const float* a2 = base + (size_t)fi[2] * 3;
        const float v0x = a0[0], v0y = a0[1], v0z = a0[2];
        const float v1x = a1[0], v1y = a1[1], v1z = a1[2];
        const float v2x = a2[0], v2y = a2[1], v2z = a2[2];
        const float cx = v0y * v1z - v0z * v1y;
        const float cy = v0z * v1x - v0x * v1z;
        const float cz = v0x * v1y - v0y * v1x;
        const float fv = (cx * v2x + cy * v2y + cz * v2z) * (1.0f / 6.0f);
        acc += (double)fv;
    }
    sred[tid] = acc;
    __syncthreads();
    #pragma unroll
    for (int s = 128; s >= 1; s >>= 1) {
        if (tid < s) sred[tid] += sred[tid + s];
        __syncthreads();
    }
    if (tid == 0) {
        float vols = fabsf((float)sred[0]);
        float d = vols - tv[b];
        out[4 + b] = d * d;
    }
}

// ---------------------------------------------------------------------------
// Finalize chamfer: 32 lanes, lane = b*8 + p. Sum the 16 tile partials,
// per_proj = sum / max(cnt,1), mean over p -> out[b].
// ---------------------------------------------------------------------------
__global__ void finalize_kernel(float* __restrict__ out) {
    const int lane = threadIdx.x;           // 0..31
    float s = 0.0f, c = 0.0f;
    #pragma unroll
    for (int t = 0; t < TILES; ++t) {
        s += g_part_sum[lane * TILES + t];
        c += g_part_cnt[lane * TILES + t];
    }
    float pp = s / fmaxf(c, 1.0f);
    #pragma unroll
    for (int off = 4; off >= 1; off >>= 1)
        pp += __shfl_down_sync(0xffffffffu, pp, off, 8);
    if ((lane & 7) == 0) out[lane >> 3] = pp * (1.0f / 8.0f);
}

// ---------------------------------------------------------------------------
extern "C" void kernel_launch(void* const* d_in, const int* in_sizes, int n_in,
                              void* d_out, int out_size)
{
    const float* xs    = (const float*)d_in[0];   // (4,2048,3)
    const float* pm    = (const float*)d_in[1];   // (8,3,4)
    const float* em    = (const float*)d_in[2];   // (4,8,2048,2)
    const int*   lens  = (const int*)  d_in[3];   // (4,8)
    const void*  bmask =               d_in[4];   // (4,8,2048) bool (layout detected)
    const int*   faces = (const int*)  d_in[5];   // (4,4096,3)
    const float* tv    = (const float*)d_in[6];   // (4,)
    float* out = (float*)d_out;                   // [chamfer(4), vol_error(4)]

    detect_mask_kernel<<<1, 256>>>((const unsigned char*)bmask);
    chamfer_kernel<<<dim3(TILES, Pn, Bn), TPB>>>(xs, pm, em, lens, bmask);
    volume_kernel<<<Bn, 256>>>(xs, faces, tv, out);
    finalize_kernel<<<1, 32>>>(out);
}

// round 2
// speedup vs baseline: 1.9634x; 1.9634x over previous
#include <cuda_runtime.h>

#define Bn 4
#define Pn 8
#define Vn 2048
#define En 2048
#define Fn 4096
#define TILES 8
#define TPB 64               // 2 warps
#define VPT 4                // vertices per thread (TPB*VPT = 256 verts/block)
#define CHAM_BLOCKS (Bn * Pn * TILES)   // 256
#define BIGF 3.402823466e38f

__device__ float g_part_sum[Bn * Pn * TILES];
__device__ float g_part_cnt[Bn * Pn * TILES];
__device__ unsigned int g_counter;   // never reset; +CHAM_BLOCKS per launch

// ---------------------------------------------------------------------------
// packed fp32x2 helpers (sm_103a FFMA2)
// ---------------------------------------------------------------------------
__device__ __forceinline__ unsigned long long bcast2(float v) {
    unsigned long long r;
    asm("mov.b64 %0, {%1, %1};" : "=l"(r) : "f"(v));
    return r;
}

// d2[k] = px*x2[k] + py*y2[k] + c2[k]  for k=0,1 ; fold into mins
__device__ __forceinline__ void edge2(float& m0, float& m1,
                                      unsigned long long pxx, unsigned long long pyy,
                                      unsigned long long x2, unsigned long long y2,
                                      unsigned long long c2)
{
    float d0, d1;
    asm("{\n\t"
        ".reg .b64 t;\n\t"
        "fma.rn.f32x2 t, %2, %3, %4;\n\t"
        "fma.rn.f32x2 t, %5, %6, t;\n\t"
        "mov.b64 {%0, %1}, t;\n\t"
        "}"
        : "=f"(d0), "=f"(d1)
        : "l"(pyy), "l"(y2), "l"(c2), "l"(pxx), "l"(x2));
    m0 = fminf(m0, d0);
    m1 = fminf(m1, d1);
}

// ---------------------------------------------------------------------------
// Single fused kernel. Blocks [0, 256): chamfer. Blocks [256, 260): volume.
// Last-finishing chamfer block also does the chamfer finalize.
// ---------------------------------------------------------------------------
__global__ void __launch_bounds__(TPB)
fused_kernel(const float* __restrict__ xs,
             const float* __restrict__ pm,
             const float* __restrict__ em,
             const int*   __restrict__ lens,
             const void*  __restrict__ bmask,
             const int*   __restrict__ faces,
             const float* __restrict__ tv,
             float* __restrict__ out)
{
    const int bx  = blockIdx.x;
    const int tid = threadIdx.x;

    // =========================== VOLUME BLOCKS ============================
    if (bx >= CHAM_BLOCKS) {
        __shared__ double sred[TPB];
        const int b = bx - CHAM_BLOCKS;
        const float* base = xs + (size_t)b * Vn * 3;
        double acc = 0.0;
        for (int f = tid; f < Fn; f += TPB) {
            const int* fi = faces + ((size_t)b * Fn + f) * 3;
            const float* a0 = base + (size_t)fi[0] * 3;
            const float* a1 = base + (size_t)fi[1] * 3;
            const float* a2 = base + (size_t)fi[2] * 3;
            const float v0x = a0[0], v0y = a0[1], v0z = a0[2];
            const float v1x = a1[0], v1y = a1[1], v1z = a1[2];
            const float v2x = a2[0], v2y = a2[1], v2z = a2[2];
            const float cx = v0y * v1z - v0z * v1y;
            const float cy = v0z * v1x - v0x * v1z;
            const float cz = v0x * v1y - v0y * v1x;
            acc += (double)((cx * v2x + cy * v2y + cz * v2z) * (1.0f / 6.0f));
        }
        sred[tid] = acc;
        __syncthreads();
        #pragma unroll
        for (int s = TPB / 2; s >= 1; s >>= 1) {
            if (tid < s) sred[tid] += sred[tid + s];
            __syncthreads();
        }
        if (tid == 0) {
            float vols = fabsf((float)sred[0]);
            float d = vols - tv[b];
            out[4 + b] = d * d;
        }
        return;
    }

    // =========================== CHAMFER BLOCKS ===========================
    // edge table as SoA float2 pairs: c = |e|^2, x = -2ex, y = -2ey
    __shared__ float2 s_c[En / 2];
    __shared__ float2 s_x[En / 2];
    __shared__ float2 s_y[En / 2];
    __shared__ float  s_rs[2], s_rc[2];
    __shared__ int    s_last;

    const int tile = bx & (TILES - 1);
    const int p    = (bx >> 3) & (Pn - 1);
    const int b    = bx >> 6;

    // ---- preload + transform edge table (pairs of edges) ----
    const float4* embase4 = (const float4*)(em + ((size_t)(b * Pn + p)) * En * 2);
    #pragma unroll
    for (int i = tid; i < En / 2; i += TPB) {
        float4 e4 = embase4[i];                 // ex0, ey0, ex1, ey1
        s_c[i] = make_float2(fmaf(e4.x, e4.x, e4.y * e4.y),
                             fmaf(e4.z, e4.z, e4.w * e4.w));
        s_x[i] = make_float2(-2.0f * e4.x, -2.0f * e4.z);
        s_y[i] = make_float2(-2.0f * e4.y, -2.0f * e4.w);
    }

    // ---- per-block boundary_mask layout detection (first 4KB, shared by all) ----
    // int32-widened bool: every byte at offset %4 != 0 is zero -> word & 0xFFFFFF00 == 0
    unsigned int scan = 0;
    {
        const unsigned int* mw = (const unsigned int*)bmask;
        #pragma unroll
        for (int i = tid; i < 1024; i += TPB)
            scan |= (mw[i] & 0xFFFFFF00u);
    }
    const int mask_is_bytes = __syncthreads_or(scan != 0);  // also the preload barrier

    // ---- per-thread vertex projections (VPT verts, stride TPB) ----
    const float* M = pm + p * 12;
    const int vbase = tile * (TPB * VPT);
    float px[VPT], py[VPT], pp[VPT];
    unsigned long long pxx[VPT], pyy[VPT];
    #pragma unroll
    for (int j = 0; j < VPT; ++j) {
        const int v = vbase + j * TPB + tid;
        const float* xv = xs + ((size_t)b * Vn + v) * 3;
        const float x = xv[0], y = xv[1], z = xv[2];
        const float q0 = M[0] * x + M[1] * y + M[2]  * z + M[3];
        const float q1 = M[4] * x + M[5] * y + M[6]  * z + M[7];
        const float q2 = M[8] * x + M[9] * y + M[10] * z + M[11];
        px[j] = q0 / q2;
        py[j] = q1 / q2;
        pp[j] = fmaf(px[j], px[j], py[j] * py[j]);
        pxx[j] = bcast2(px[j]);
        pyy[j] = bcast2(py[j]);
    }

    // ---- main loop: 2 edges x VPT verts per iteration ----
    const int L  = lens[b * Pn + p];
    const int P2 = L >> 1;
    float m0a = BIGF, m0b = BIGF, m1a = BIGF, m1b = BIGF;
    float m2a = BIGF, m2b = BIGF, m3a = BIGF, m3b = BIGF;

    const unsigned long long* sc = (const unsigned long long*)s_c;
    const unsigned long long* sx = (const unsigned long long*)s_x;
    const unsigned long long* sy = (const unsigned long long*)s_y;

    #pragma unroll 4
    for (int i = 0; i < P2; ++i) {
        const unsigned long long c2 = sc[i];
        const unsigned long long x2 = sx[i];
        const unsigned long long y2 = sy[i];
        edge2(m0a, m0b, pxx[0], pyy[0], x2, y2, c2);
        edge2(m1a, m1b, pxx[1], pyy[1], x2, y2, c2);
        edge2(m2a, m2b, pxx[2], pyy[2], x2, y2, c2);
        edge2(m3a, m3b, pxx[3], pyy[3], x2, y2, c2);
    }
    if (L & 1) {                       // odd trailing edge
        const int i = P2;
        const float c = s_c[i].x, xx = s_x[i].x, yy = s_y[i].x;
        m0a = fminf(m0a, fmaf(px[0], xx, fmaf(py[0], yy, c)));
        m1a = fminf(m1a, fmaf(px[1], xx, fmaf(py[1], yy, c)));
        m2a = fminf(m2a, fmaf(px[2], xx, fmaf(py[2], yy, c)));
        m3a = fminf(m3a, fmaf(px[3], xx, fmaf(py[3], yy, c)));
    }

    float dmin[VPT];
    dmin[0] = fminf(m0a, m0b) + pp[0];
    dmin[1] = fminf(m1a, m1b) + pp[1];
    dmin[2] = fminf(m2a, m2b) + pp[2];
    dmin[3] = fminf(m3a, m3b) + pp[3];

    // ---- boundary mask + local accumulation ----
    float cs = 0.0f, cc = 0.0f;
    #pragma unroll
    for (int j = 0; j < VPT; ++j) {
        const int v = vbase + j * TPB + tid;
        const int midx = (b * Pn + p) * Vn + v;
        float w;
        if (mask_is_bytes) w = (((const unsigned char*)bmask)[midx] != 0) ? 1.0f : 0.0f;
        else               w = (((const int*)bmask)[midx] != 0) ? 1.0f : 0.0f;
        cs = fmaf(w, dmin[j], cs);
        cc += w;
    }

    // ---- block reduction (deterministic fixed tree) ----
    #pragma unroll
    for (int off = 16; off >= 1; off >>= 1) {
        cs += __shfl_down_sync(0xffffffffu, cs, off);
        cc += __shfl_down_sync(0xffffffffu, cc, off);
    }
    const int wid = tid >> 5;
    if ((tid & 31) == 0) { s_rs[wid] = cs; s_rc[wid] = cc; }
    __syncthreads();

    if (tid == 0) {
        const int slot = (b * Pn + p) * TILES + tile;
        g_part_sum[slot] = s_rs[0] + s_rs[1];
        g_part_cnt[slot] = s_rc[0] + s_rc[1];
        __threadfence();
        unsigned int old = atomicAdd(&g_counter, 1u);
        s_last = (((old + 1u) & (CHAM_BLOCKS - 1u)) == 0u) ? 1 : 0;
    }
    __syncthreads();

    // ---- last block finalizes chamfer means ----
    if (s_last && tid < 32) {
        __threadfence();
        const int lane = tid;                    // lane = b*Pn + p
        float s = 0.0f, c = 0.0f;
        #pragma unroll
        for (int t = 0; t < TILES; ++t) {
            s += g_part_sum[lane * TILES + t];
            c += g_part_cnt[lane * TILES + t];
        }
        float ppj = s / fmaxf(c, 1.0f);
        #pragma unroll
        for (int off = 4; off >= 1; off >>= 1)
            ppj += __shfl_down_sync(0xffffffffu, ppj, off, 8);
        if ((lane & 7) == 0) out[lane >> 3] = ppj * (1.0f / Pn);
    }
}

// ---------------------------------------------------------------------------
extern "C" void kernel_launch(void* const* d_in, const int* in_sizes, int n_in,
                              void* d_out, int out_size)
{
    const float* xs    = (const float*)d_in[0];   // (4,2048,3)
    const float* pm    = (const float*)d_in[1];   // (8,3,4)
    const float* em    = (const float*)d_in[2];   // (4,8,2048,2)
    const int*   lens  = (const int*)  d_in[3];   // (4,8)
    const void*  bmask =               d_in[4];   // (4,8,2048) bool (layout auto-detected)
    const int*   faces = (const int*)  d_in[5];   // (4,4096,3)
    const float* tv    = (const float*)d_in[6];   // (4,)
    float* out = (float*)d_out;                   // [chamfer(4), vol_error(4)]

    fused_kernel<<<CHAM_BLOCKS + Bn, TPB>>>(xs, pm, em, lens, bmask, faces, tv, out);
}